// round 3
// baseline (speedup 1.0000x reference)
#include <cuda_runtime.h>
#include <math.h>

#define Bb 2
#define Hh 16
#define Ss 2048
#define Dd 64
#define TQ 16
#define TPB 512
#define KT 256            // keys per staged tile
#define NTILE (Ss/KT)     // 8
#define SCP 2049          // padded pitch for score strip (bank-conflict-free column reads)
#define INV_TEMP 0.125f
#define NEGINF -1e9f

// SMEM float offsets
#define OFF_SQP 0                      // 8 row-pairs x 64 d x float2 = 1024 floats (q pre-scaled, pre-paired)
#define OFF_SC  1024                   // 16 x 2049 = 32784 floats
#define OFF_KT  (OFF_SC + TQ*SCP)      // 33808 : 256x64 = 16384 floats (K tile, then V tile, then PV partials)
#define OFF_MSK (OFF_KT + KT*Dd)       // 50192 : 64 words mask bitmap
#define SMEM_FLOATS (OFF_MSK + 64)     // 50256 floats = 201024 B

typedef unsigned long long ull;

__device__ __forceinline__ ull pk2(float lo, float hi) {
    ull r; asm("mov.b64 %0,{%1,%2};" : "=l"(r) : "f"(lo), "f"(hi)); return r;
}
__device__ __forceinline__ void upk2(ull v, float& lo, float& hi) {
    asm("mov.b64 {%0,%1},%2;" : "=f"(lo), "=f"(hi) : "l"(v));
}
__device__ __forceinline__ ull fma2(ull a, ull b, ull c) {
    ull d; asm("fma.rn.f32x2 %0,%1,%2,%3;" : "=l"(d) : "l"(a), "l"(b), "l"(c)); return d;
}

__global__ void __launch_bounds__(TPB, 1)
attn_kernel(const float* __restrict__ Q, const float* __restrict__ K,
            const float* __restrict__ V, const float* __restrict__ SENT,
            const int* __restrict__ MASK,
            float* __restrict__ OUT, float* __restrict__ ATTN)
{
    extern __shared__ float smem[];
    float*    sqp   = smem + OFF_SQP;           // [pair p][d] as float2 -> ull
    float*    sc    = smem + OFF_SC;            // [TQ][SCP]
    float*    kt    = smem + OFF_KT;            // staged K/V tile (swizzled), later partials
    unsigned* maskw = (unsigned*)(smem + OFF_MSK);

    const int tid  = threadIdx.x;
    const int lane = tid & 31;
    const int wid  = tid >> 5;
    const int q0   = blockIdx.x * TQ;
    const int h    = blockIdx.y;
    const int b    = blockIdx.z;
    const size_t head_off = ((size_t)(b * Hh + h)) * (size_t)Ss;

    // ---- load q tile: pre-scale by 1/TEMP, store row-paired: sqp[p][d] = {q[2p][d], q[2p+1][d]} ----
    {
        const float* qbase = Q + (head_off + (size_t)q0) * Dd;
        for (int i = tid; i < TQ * Dd; i += TPB) {
            int r = i / Dd, d = i % Dd;
            float v = qbase[i] * INV_TEMP;
            // pair p = r>>1, component r&1
            ((float*)sqp)[((r >> 1) * Dd + d) * 2 + (r & 1)] = v;
        }
        // mask bitmap: 2048 bits
        const int* mrow = MASK + b * Ss;
        #pragma unroll
        for (int t = 0; t < 4; t++) {
            int j = t * TPB + tid;
            unsigned bal = __ballot_sync(0xFFFFFFFFu, mrow[j] != 0);
            if (lane == 0) maskw[t * 16 + wid] = bal;
        }
    }
    __syncthreads();

    const float4* k4base = (const float4*)(K + head_off * Dd);
    const float4* v4base = (const float4*)(V + head_off * Dd);
    float4* kt4 = (float4*)kt;

    // ================= Phase 1: scores = (q/T) @ K^T =================
    // thread -> (key jl = tid&255 within tile, row-group rg = tid>>8 : rows rg*8..rg*8+7)
    {
        const int jl = tid & 255;
        const int rg = tid >> 8;
        const ull* qp = (const ull*)sqp;

        for (int t = 0; t < NTILE; t++) {
            const int base = t * KT;
            // stage K tile, coalesced gmem -> swizzled smem
            const float4* src = k4base + (size_t)base * (Dd / 4);
            #pragma unroll
            for (int i = tid; i < KT * (Dd / 4); i += TPB) {
                int jj = i >> 4, cc = i & 15;
                kt4[jj * 16 + (cc ^ (jj & 7))] = src[i];
            }
            __syncthreads();

            const int j = base + jl;
            const bool live = (maskw[j >> 5] >> (j & 31)) & 1u;
            if (live) {
                ull acc[4] = {0ull, 0ull, 0ull, 0ull};
                const float4* krow = kt4 + jl * 16;
                const int sw = jl & 7;
                #pragma unroll
                for (int c = 0; c < 16; c++) {
                    float4 kv = krow[c ^ sw];
                    ull s0 = pk2(kv.x, kv.x), s1 = pk2(kv.y, kv.y);
                    ull s2 = pk2(kv.z, kv.z), s3 = pk2(kv.w, kv.w);
                    #pragma unroll
                    for (int p = 0; p < 4; p++) {
                        const ull* qq = qp + ((rg * 4 + p) * Dd + 4 * c);
                        ull a = acc[p];
                        a = fma2(qq[0], s0, a);
                        a = fma2(qq[1], s1, a);
                        a = fma2(qq[2], s2, a);
                        a = fma2(qq[3], s3, a);
                        acc[p] = a;
                    }
                }
                #pragma unroll
                for (int p = 0; p < 4; p++) {
                    float lo, hi; upk2(acc[p], lo, hi);
                    sc[(rg * 8 + 2 * p)     * SCP + j] = lo;
                    sc[(rg * 8 + 2 * p + 1) * SCP + j] = hi;
                }
            } else {
                #pragma unroll
                for (int r = 0; r < 8; r++) sc[(rg * 8 + r) * SCP + j] = NEGINF;
            }
            __syncthreads();
        }
    }

    // ===== Phase 2: probs = exp(s-m)*sent / sum ; write ATTN =====
    {
        const int r = wid;                 // 16 warps = 16 rows
        float* row = sc + r * SCP;
        float m = -INFINITY;
        for (int jj = lane; jj < Ss; jj += 32) m = fmaxf(m, row[jj]);
        #pragma unroll
        for (int o = 16; o > 0; o >>= 1) m = fmaxf(m, __shfl_xor_sync(0xFFFFFFFFu, m, o));

        const float* srow = SENT + b * Ss;
        float sum = 0.0f;
        for (int jj = lane; jj < Ss; jj += 32) {
            float p = __expf(row[jj] - m) * srow[jj];
            row[jj] = p;
            sum += p;
        }
        #pragma unroll
        for (int o = 16; o > 0; o >>= 1) sum += __shfl_xor_sync(0xFFFFFFFFu, sum, o);
        const float inv = 1.0f / sum;

        float* arow = ATTN + (head_off + (size_t)(q0 + r)) * (size_t)Ss;
        for (int jj = lane; jj < Ss; jj += 32) {
            float a = row[jj] * inv;
            row[jj] = a;
            arow[jj] = a;
        }
    }
    __syncthreads();

    // ================= Phase 3: out = probs @ V =================
    // thread -> (jg = wid, lane: r = lane>>1, dh = lane&1)
    // acc[c] holds out[r][(dh*8+c)*4 .. +3]; all lanes of a warp share the same j.
    {
        const int jg = wid;
        const int r  = lane >> 1;
        const int dh = lane & 1;
        float4 acc[8];
        #pragma unroll
        for (int c = 0; c < 8; c++) acc[c] = make_float4(0.f, 0.f, 0.f, 0.f);

        for (int t = 0; t < NTILE; t++) {
            const int base = t * KT;
            // stage V tile (reuse kt buffer)
            const float4* src = v4base + (size_t)base * (Dd / 4);
            #pragma unroll
            for (int i = tid; i < KT * (Dd / 4); i += TPB) {
                int jj = i >> 4, cc = i & 15;
                kt4[jj * 16 + (cc ^ (jj & 7))] = src[i];
            }
            __syncthreads();

            #pragma unroll 4
            for (int i = 0; i < 16; i++) {
                const int jl = (jg << 4) + i;
                const int j  = base + jl;
                if ((maskw[j >> 5] >> (j & 31)) & 1u) {
                    const float a = sc[r * SCP + j];
                    const float4* vrow = kt4 + jl * 16;
                    const int sw = jl & 7;
                    #pragma unroll
                    for (int c = 0; c < 8; c++) {
                        float4 vv = vrow[(dh * 8 + c) ^ sw];
                        acc[c].x = fmaf(a, vv.x, acc[c].x);
                        acc[c].y = fmaf(a, vv.y, acc[c].y);
                        acc[c].z = fmaf(a, vv.z, acc[c].z);
                        acc[c].w = fmaf(a, vv.w, acc[c].w);
                    }
                }
            }
            __syncthreads();
        }

        // store partials (swizzled to avoid bank camping), then reduce over 16 jg
        float4* part4 = (float4*)kt;
        #pragma unroll
        for (int c = 0; c < 8; c++) part4[tid * 8 + (c ^ (tid & 7))] = acc[c];
        __syncthreads();

        if (tid < 256) {
            const int rr = tid >> 4;         // row
            const int cq = tid & 15;         // d chunk 0..15
            const int dh2 = cq >> 3, cc = cq & 7;
            float4 s = make_float4(0.f, 0.f, 0.f, 0.f);
            #pragma unroll
            for (int g = 0; g < 16; g++) {
                const int src_tid = g * 32 + rr * 2 + dh2;
                float4 p = part4[src_tid * 8 + (cc ^ (src_tid & 7))];
                s.x += p.x; s.y += p.y; s.z += p.z; s.w += p.w;
            }
            float4* orow = (float4*)(OUT + (head_off + (size_t)(q0 + rr)) * Dd);
            orow[cq] = s;
        }
    }
}

extern "C" void kernel_launch(void* const* d_in, const int* in_sizes, int n_in,
                              void* d_out, int out_size)
{
    const float* q    = (const float*)d_in[0];
    const float* k    = (const float*)d_in[1];
    const float* v    = (const float*)d_in[2];
    const float* sent = (const float*)d_in[3];
    const int*   mask = (const int*)d_in[4];

    float* out  = (float*)d_out;                    // [B,H,S,D]
    float* attn = out + (size_t)Bb * Hh * Ss * Dd;  // [B,H,S,S]

    size_t smem_bytes = (size_t)SMEM_FLOATS * sizeof(float); // 201024 B
    cudaFuncSetAttribute(attn_kernel,
                         cudaFuncAttributeMaxDynamicSharedMemorySize,
                         (int)smem_bytes);

    dim3 grid(Ss / TQ, Hh, Bb);
    attn_kernel<<<grid, TPB, smem_bytes>>>(q, k, v, sent, mask, out, attn);
}